// round 5
// baseline (speedup 1.0000x reference)
#include <cuda_runtime.h>
#include <cstdint>

// LSHGaussian, tf32 mma.sync with warp specialization:
//   - 4 compute warps x 32 rows (2 m16n8k8 m-tiles share each B fragment,
//     halving smem B-fragment traffic vs 8x16)
//   - 4 producer warps stage the U tile (fp32 -> tf32) + ref features into
//     double-buffered smem, handed off with named barriers.
// out = P @ U - U,  P[i,j] = exp(-0.5*||ref_i-ref_j||^2).
// N=16384, C=64, D_ref=5. grid=128 CTAs x 256 threads.

#define N_PTS  16384
#define CCH    64
#define BM     128
#define BK     128
#define TPB    256
#define NTILES (N_PTS / BK)
#define USTR   72          // U-tile row stride in floats (conflict-free B loads)

#define US_BYTES (BK * USTR * 4)     // 36864
#define RS_BYTES (BK * 8 * 4)        // 4096
#define SMEM_TOTAL (2 * US_BYTES + 2 * RS_BYTES)   // 81920

// named barriers: 1,2 = FULL[buf], 3,4 = EMPTY[buf]
#define BAR_SYNC(id)   asm volatile("bar.sync %0, %1;"   :: "n"(id), "n"(TPB) : "memory")
#define BAR_ARRIVE(id) asm volatile("bar.arrive %0, %1;" :: "n"(id), "n"(TPB) : "memory")

__device__ __forceinline__ float ex2f(float x) {
    float r; asm("ex2.approx.ftz.f32 %0, %1;" : "=f"(r) : "f"(x)); return r;
}
__device__ __forceinline__ uint32_t cvt_tf32(float x) {
    uint32_t r; asm("cvt.rna.tf32.f32 %0, %1;" : "=r"(r) : "f"(x)); return r;
}

__global__ void __launch_bounds__(TPB, 1)
lsh_mma_ws_kernel(const float* __restrict__ U, const float* __restrict__ ref,
                  float* __restrict__ out)
{
    extern __shared__ __align__(16) char smem[];
    uint32_t* const UsB[2] = { (uint32_t*)smem, (uint32_t*)(smem + US_BYTES) };
    float*    const RsB[2] = { (float*)(smem + 2 * US_BYTES),
                               (float*)(smem + 2 * US_BYTES + RS_BYTES) };

    const int tid  = threadIdx.x;
    const int wid  = tid >> 5;
    const int lane = tid & 31;
    const float L2E = 1.4426950408889634f;

    if (wid < 4) {
        // ───────────────────────── consumer: 32 rows per warp ──────────────
        const int g    = lane >> 2;       // 0..7
        const int kin  = lane & 3;        // 0..3
        const int rbase = blockIdx.x * BM + wid * 32;

        // 4 A-rows per thread: offsets rr*8 + g (rr=0,1 -> m-tile0; 2,3 -> m-tile1)
        float ri[4][5], bi[4];
        #pragma unroll
        for (int rr = 0; rr < 4; ++rr) {
            const float* rp = ref + (size_t)(rbase + rr * 8 + g) * 5;
            float s = 0.f;
            #pragma unroll
            for (int k = 0; k < 5; ++k) {
                float v = rp[k];
                s = fmaf(v, v, s);
                ri[rr][k] = v * L2E;
            }
            bi[rr] = -0.5f * L2E * s;
        }

        float c[2][8][4];
        #pragma unroll
        for (int mt = 0; mt < 2; ++mt)
            #pragma unroll
            for (int nt = 0; nt < 8; ++nt)
                #pragma unroll
                for (int q = 0; q < 4; ++q) c[mt][nt][q] = 0.f;

        for (int t = 0; t < NTILES; ++t) {
            const int buf = t & 1;
            if (buf) BAR_SYNC(2); else BAR_SYNC(1);       // wait FULL[buf]
            const uint32_t* __restrict__ Ub = UsB[buf];
            const float*    __restrict__ R  = RsB[buf];

            #pragma unroll 4
            for (int kc = 0; kc < BK / 8; ++kc) {
                const int jA = kc * 8 + kin;
                const int jB = jA + 4;

                float4 rA0 = *(const float4*)&R[jA * 8];
                float4 rA1 = *(const float4*)&R[jA * 8 + 4];
                float4 rB0 = *(const float4*)&R[jB * 8];
                float4 rB1 = *(const float4*)&R[jB * 8 + 4];

                uint32_t aA[4], aB[4];
                #pragma unroll
                for (int rr = 0; rr < 4; ++rr) {
                    float tA = bi[rr] + rA1.y;
                    float tB = bi[rr] + rB1.y;
                    tA = fmaf(ri[rr][0], rA0.x, tA); tB = fmaf(ri[rr][0], rB0.x, tB);
                    tA = fmaf(ri[rr][1], rA0.y, tA); tB = fmaf(ri[rr][1], rB0.y, tB);
                    tA = fmaf(ri[rr][2], rA0.z, tA); tB = fmaf(ri[rr][2], rB0.z, tB);
                    tA = fmaf(ri[rr][3], rA0.w, tA); tB = fmaf(ri[rr][3], rB0.w, tB);
                    tA = fmaf(ri[rr][4], rA1.x, tA); tB = fmaf(ri[rr][4], rB1.x, tB);
                    aA[rr] = cvt_tf32(ex2f(fminf(tA, 0.f)));
                    aB[rr] = cvt_tf32(ex2f(fminf(tB, 0.f)));
                }

                const uint32_t* uA = &Ub[jA * USTR + g];
                const uint32_t* uBp = &Ub[jB * USTR + g];
                #pragma unroll
                for (int nt = 0; nt < 8; ++nt) {
                    uint32_t b0 = uA[nt * 8];
                    uint32_t b1 = uBp[nt * 8];
                    asm volatile(
                        "mma.sync.aligned.m16n8k8.row.col.f32.tf32.tf32.f32 "
                        "{%0,%1,%2,%3}, {%4,%5,%6,%7}, {%8,%9}, {%0,%1,%2,%3};"
                        : "+f"(c[0][nt][0]), "+f"(c[0][nt][1]),
                          "+f"(c[0][nt][2]), "+f"(c[0][nt][3])
                        : "r"(aA[0]), "r"(aA[1]), "r"(aB[0]), "r"(aB[1]),
                          "r"(b0), "r"(b1));
                    asm volatile(
                        "mma.sync.aligned.m16n8k8.row.col.f32.tf32.tf32.f32 "
                        "{%0,%1,%2,%3}, {%4,%5,%6,%7}, {%8,%9}, {%0,%1,%2,%3};"
                        : "+f"(c[1][nt][0]), "+f"(c[1][nt][1]),
                          "+f"(c[1][nt][2]), "+f"(c[1][nt][3])
                        : "r"(aA[2]), "r"(aA[3]), "r"(aB[2]), "r"(aB[3]),
                          "r"(b0), "r"(b1));
                }
            }
            if (buf) BAR_ARRIVE(4); else BAR_ARRIVE(3);    // signal EMPTY[buf]
        }

        // Epilogue: out = C - U.
        const int n0 = 2 * kin;
        #pragma unroll
        for (int mt = 0; mt < 2; ++mt) {
            const int rl = rbase + mt * 16 + g;
            const int rh = rl + 8;
            #pragma unroll
            for (int nt = 0; nt < 8; ++nt) {
                const int col = nt * 8 + n0;
                float2 ul = *(const float2*)(U + (size_t)rl * CCH + col);
                float2 uh = *(const float2*)(U + (size_t)rh * CCH + col);
                float2 ol, oh;
                ol.x = c[mt][nt][0] - ul.x; ol.y = c[mt][nt][1] - ul.y;
                oh.x = c[mt][nt][2] - uh.x; oh.y = c[mt][nt][3] - uh.y;
                *(float2*)(out + (size_t)rl * CCH + col) = ol;
                *(float2*)(out + (size_t)rh * CCH + col) = oh;
            }
        }
    } else {
        // ───────────────────────── producer: stage tiles ────────────────────
        const int p = tid - 128;            // 0..127
        for (int t = 0; t < NTILES; ++t) {
            const int buf = t & 1;
            if (t >= 2) { if (buf) BAR_SYNC(4); else BAR_SYNC(3); }  // wait EMPTY[buf]

            const int j0 = t * BK;
            uint32_t* __restrict__ Ud = UsB[buf];
            const float4* Ug = (const float4*)(U + (size_t)j0 * CCH);
            #pragma unroll
            for (int it = 0; it < 16; ++it) {
                int f = it * 128 + p;            // 0..2047 float4s
                int j = f >> 4, c4 = f & 15;
                float4 v = Ug[f];
                uint4 w;
                w.x = cvt_tf32(v.x); w.y = cvt_tf32(v.y);
                w.z = cvt_tf32(v.z); w.w = cvt_tf32(v.w);
                *(uint4*)&Ud[j * USTR + c4 * 4] = w;
            }
            {
                const float* rj = ref + (size_t)(j0 + p) * 5;
                float r0 = rj[0], r1 = rj[1], r2 = rj[2], r3 = rj[3], r4 = rj[4];
                float s = fmaf(r0, r0, fmaf(r1, r1,
                          fmaf(r2, r2, fmaf(r3, r3, r4 * r4))));
                float* R = RsB[buf] + p * 8;
                R[0] = r0; R[1] = r1; R[2] = r2; R[3] = r3;
                R[4] = r4; R[5] = -0.5f * L2E * s;
            }
            asm volatile("membar.cta;" ::: "memory");
            if (buf) BAR_ARRIVE(2); else BAR_ARRIVE(1);    // signal FULL[buf]
        }
    }
}

extern "C" void kernel_launch(void* const* d_in, const int* in_sizes, int n_in,
                              void* d_out, int out_size)
{
    const float* U   = (const float*)d_in[0];   // [N, 64]
    const float* ref = (const float*)d_in[1];   // [N, 5]
    float* out = (float*)d_out;                 // [N, 64]
    (void)in_sizes; (void)n_in; (void)out_size;

    cudaFuncSetAttribute(lsh_mma_ws_kernel,
                         cudaFuncAttributeMaxDynamicSharedMemorySize, SMEM_TOTAL);
    lsh_mma_ws_kernel<<<N_PTS / BM, TPB, SMEM_TOTAL>>>(U, ref, out);
}

// round 7
// speedup vs baseline: 1.1442x; 1.1442x over previous
#include <cuda_runtime.h>
#include <cstdint>

// LSHGaussian, tf32 mma.sync, split-j warp layout:
//   8 warps: warps w and w+4 own the SAME 32 rows, but j-halves 0/1 of the
//   128-j tile. B fragments feed 2 m-tiles (2x less smem B traffic than R4),
//   all 8 warps compute (unlike R5). Partial sums reduced via smem once.
//   Weight pairs (jA,jB) computed with packed f32x2 FMA chains.
//   Double-buffered staging, LDG prefetch before compute, 1 sync/tile.
// out = P @ U - U,  P[i,j] = exp(-0.5*||ref_i-ref_j||^2).
// N=16384, C=64, D_ref=5. grid=128 CTAs x 256 threads.

#define N_PTS  16384
#define CCH    64
#define BM     128
#define BK     128
#define TPB    256
#define NTILES (N_PTS / BK)
#define USTR   72          // U-tile row stride in floats (conflict-free B loads)

#define US_BYTES (BK * USTR * 4)       // 36864
#define R2_BYTES (16 * 6 * 4 * 8)      // 3072: [kc16][feat6][kin4] float2
#define OFF_US0  0
#define OFF_US1  US_BYTES
#define OFF_R20  (2 * US_BYTES)
#define OFF_R21  (2 * US_BYTES + R2_BYTES)
#define SMEM_TOTAL (2 * US_BYTES + 2 * R2_BYTES)   // 79872

typedef unsigned long long u64;

__device__ __forceinline__ float ex2f(float x) {
    float r; asm("ex2.approx.ftz.f32 %0, %1;" : "=f"(r) : "f"(x)); return r;
}
__device__ __forceinline__ uint32_t cvt_tf32(float x) {
    uint32_t r; asm("cvt.rna.tf32.f32 %0, %1;" : "=r"(r) : "f"(x)); return r;
}
#define FMA2(acc, a, b) asm("fma.rn.f32x2 %0, %1, %2, %0;" : "+l"(acc) : "l"(a), "l"(b))
#define ADD2(d, a, b)   asm("add.rn.f32x2 %0, %1, %2;" : "=l"(d) : "l"(a), "l"(b))
#define PACKB(d, f)     asm("mov.b64 %0, {%1, %1};" : "=l"(d) : "f"(f))
#define UNPK(lo, hi, v) asm("mov.b64 {%0, %1}, %2;" : "=f"(lo), "=f"(hi) : "l"(v))
#define MMA(cc, a0, a1, a2, a3, b0, b1) \
    asm volatile("mma.sync.aligned.m16n8k8.row.col.f32.tf32.tf32.f32 " \
                 "{%0,%1,%2,%3}, {%4,%5,%6,%7}, {%8,%9}, {%0,%1,%2,%3};" \
                 : "+f"((cc)[0]), "+f"((cc)[1]), "+f"((cc)[2]), "+f"((cc)[3]) \
                 : "r"(a0), "r"(a1), "r"(a2), "r"(a3), "r"(b0), "r"(b1))

__global__ void __launch_bounds__(TPB, 1)
lsh_mma_sj_kernel(const float* __restrict__ U, const float* __restrict__ ref,
                  float* __restrict__ out)
{
    extern __shared__ __align__(16) char smem[];
    uint32_t* const UsB[2] = { (uint32_t*)(smem + OFF_US0), (uint32_t*)(smem + OFF_US1) };
    u64*      const R2B[2] = { (u64*)(smem + OFF_R20), (u64*)(smem + OFF_R21) };

    const int tid  = threadIdx.x;
    const int wid  = tid >> 5;
    const int lane = tid & 31;
    const int g    = lane >> 2;       // 0..7
    const int kin  = lane & 3;        // 0..3
    const int h    = wid >> 2;        // j-half
    const int wm   = wid & 3;         // row-block
    const float L2E = 1.4426950408889634f;
    const int rbase = blockIdx.x * BM + wm * 32;

    // 4 A-rows/thread (rr*8+g), packed-broadcast multipliers for f32x2 chains.
    u64 ri2[4][5], bi2[4];
    #pragma unroll
    for (int rr = 0; rr < 4; ++rr) {
        const float* rp = ref + (size_t)(rbase + rr * 8 + g) * 5;
        float s = 0.f;
        #pragma unroll
        for (int k = 0; k < 5; ++k) {
            float v = rp[k];
            s = fmaf(v, v, s);
            float vs = v * L2E;
            PACKB(ri2[rr][k], vs);
        }
        float b = -0.5f * L2E * s;
        PACKB(bi2[rr], b);
    }

    float c0[8][4], c1[8][4];
    #pragma unroll
    for (int nt = 0; nt < 8; ++nt)
        #pragma unroll
        for (int q = 0; q < 4; ++q) { c0[nt][q] = 0.f; c1[nt][q] = 0.f; }

    // ── prologue: stage tile 0 ──
    {
        const float4* Ug = (const float4*)U;
        uint32_t* Ud = UsB[0];
        #pragma unroll
        for (int it = 0; it < 8; ++it) {
            int f = it * TPB + tid, j = f >> 4, c4 = f & 15;
            float4 v = Ug[f];
            uint4 w = { cvt_tf32(v.x), cvt_tf32(v.y), cvt_tf32(v.z), cvt_tf32(v.w) };
            *(uint4*)&UsB[0][j * USTR + c4 * 4] = w;
        }
        (void)Ud;
        if (tid < BK) {
            const float* rj = ref + (size_t)tid * 5;
            float r[5]; float s = 0.f;
            #pragma unroll
            for (int k = 0; k < 5; ++k) { r[k] = rj[k]; s = fmaf(r[k], r[k], s); }
            int kcp = tid >> 3, slot = tid & 7, kip = slot & 3, half = slot >> 2;
            float* R2f = (float*)R2B[0];
            #pragma unroll
            for (int k = 0; k < 5; ++k)
                R2f[((kcp * 6 + k) * 4 + kip) * 2 + half] = r[k];
            R2f[((kcp * 6 + 5) * 4 + kip) * 2 + half] = -0.5f * L2E * s;
        }
    }
    __syncthreads();

    for (int t = 0; t < NTILES; ++t) {
        const int buf = t & 1, nbuf = buf ^ 1;
        const bool pfv = (t + 1 < NTILES);

        // prefetch next tile into registers (hidden under compute)
        float4 pf[8]; float pr[5];
        if (pfv) {
            const float4* Ug = (const float4*)(U + (size_t)(t + 1) * BK * CCH);
            #pragma unroll
            for (int it = 0; it < 8; ++it) pf[it] = Ug[it * TPB + tid];
            if (tid < BK) {
                const float* rj = ref + (size_t)((t + 1) * BK + tid) * 5;
                #pragma unroll
                for (int k = 0; k < 5; ++k) pr[k] = rj[k];
            }
        }

        // ── compute tile t ──
        {
            const uint32_t* __restrict__ Ubase = UsB[buf] + (h * 64 + kin) * USTR + g;
            const u64*      __restrict__ Rbase = R2B[buf] + h * 8 * 24 + kin;
            #pragma unroll
            for (int kc = 0; kc < 8; ++kc) {
                const u64* Rp = Rbase + kc * 24;
                u64 f0 = Rp[0], f1 = Rp[4], f2 = Rp[8], f3 = Rp[12], f4 = Rp[16];
                u64 fb = Rp[20];

                u64 t0, t1, t2, t3;
                ADD2(t0, fb, bi2[0]); ADD2(t1, fb, bi2[1]);
                ADD2(t2, fb, bi2[2]); ADD2(t3, fb, bi2[3]);
                FMA2(t0, ri2[0][0], f0); FMA2(t1, ri2[1][0], f0);
                FMA2(t2, ri2[2][0], f0); FMA2(t3, ri2[3][0], f0);
                FMA2(t0, ri2[0][1], f1); FMA2(t1, ri2[1][1], f1);
                FMA2(t2, ri2[2][1], f1); FMA2(t3, ri2[3][1], f1);
                FMA2(t0, ri2[0][2], f2); FMA2(t1, ri2[1][2], f2);
                FMA2(t2, ri2[2][2], f2); FMA2(t3, ri2[3][2], f2);
                FMA2(t0, ri2[0][3], f3); FMA2(t1, ri2[1][3], f3);
                FMA2(t2, ri2[2][3], f3); FMA2(t3, ri2[3][3], f3);
                FMA2(t0, ri2[0][4], f4); FMA2(t1, ri2[1][4], f4);
                FMA2(t2, ri2[2][4], f4); FMA2(t3, ri2[3][4], f4);

                // no clamp: t>0 only by rounding ulps (ex2 err < 1e-6), ref-equivalent
                float lA, lB;
                UNPK(lA, lB, t0);
                uint32_t aA0 = cvt_tf32(ex2f(lA)), aB0 = cvt_tf32(ex2f(lB));
                UNPK(lA, lB, t1);
                uint32_t aA1 = cvt_tf32(ex2f(lA)), aB1 = cvt_tf32(ex2f(lB));
                UNPK(lA, lB, t2);
                uint32_t aA2 = cvt_tf32(ex2f(lA)), aB2 = cvt_tf32(ex2f(lB));
                UNPK(lA, lB, t3);
                uint32_t aA3 = cvt_tf32(ex2f(lA)), aB3 = cvt_tf32(ex2f(lB));

                const uint32_t* uA = Ubase + kc * 8 * USTR;
                #pragma unroll
                for (int nt = 0; nt < 8; ++nt) {
                    uint32_t b0 = uA[nt * 8];
                    uint32_t b1 = uA[4 * USTR + nt * 8];
                    MMA(c0[nt], aA0, aA1, aB0, aB1, b0, b1);
                    MMA(c1[nt], aA2, aA3, aB2, aB3, b0, b1);
                }
            }
        }

        // ── stage tile t+1 into the other buffer ──
        if (pfv) {
            uint32_t* Ud = UsB[nbuf];
            #pragma unroll
            for (int it = 0; it < 8; ++it) {
                int f = it * TPB + tid, j = f >> 4, c4 = f & 15;
                uint4 w = { cvt_tf32(pf[it].x), cvt_tf32(pf[it].y),
                            cvt_tf32(pf[it].z), cvt_tf32(pf[it].w) };
                *(uint4*)&Ud[j * USTR + c4 * 4] = w;
            }
            if (tid < BK) {
                float s = fmaf(pr[0], pr[0], fmaf(pr[1], pr[1],
                          fmaf(pr[2], pr[2], fmaf(pr[3], pr[3], pr[4] * pr[4]))));
                int kcp = tid >> 3, slot = tid & 7, kip = slot & 3, half = slot >> 2;
                float* R2f = (float*)R2B[nbuf];
                #pragma unroll
                for (int k = 0; k < 5; ++k)
                    R2f[((kcp * 6 + k) * 4 + kip) * 2 + half] = pr[k];
                R2f[((kcp * 6 + 5) * 4 + kip) * 2 + half] = -0.5f * L2E * s;
            }
        }
        __syncthreads();
    }

    // ── cross-warp partial-sum reduction (warp w+4 -> warp w), then out=C-U ──
    float4* Sred = (float4*)smem;   // aliases Us buf0 (32KB <= 36KB)
    if (h == 1) {
        const int col = wm * 32 + lane;
        #pragma unroll
        for (int mt = 0; mt < 2; ++mt)
            #pragma unroll
            for (int nt = 0; nt < 8; ++nt) {
                float* cp = mt ? c1[nt] : c0[nt];
                Sred[(mt * 8 + nt) * 128 + col] = make_float4(cp[0], cp[1], cp[2], cp[3]);
            }
    }
    __syncthreads();
    if (h == 0) {
        const int col = wm * 32 + lane;
        const int n0 = 2 * kin;
        #pragma unroll
        for (int mt = 0; mt < 2; ++mt) {
            const int rl = rbase + mt * 16 + g;
            const int rh = rl + 8;
            #pragma unroll
            for (int nt = 0; nt < 8; ++nt) {
                float* cp = mt ? c1[nt] : c0[nt];
                float4 v = Sred[(mt * 8 + nt) * 128 + col];
                const int colc = nt * 8 + n0;
                float2 ul = *(const float2*)(U + (size_t)rl * CCH + colc);
                float2 uh = *(const float2*)(U + (size_t)rh * CCH + colc);
                float2 ol, oh;
                ol.x = (cp[0] + v.x) - ul.x; ol.y = (cp[1] + v.y) - ul.y;
                oh.x = (cp[2] + v.z) - uh.x; oh.y = (cp[3] + v.w) - uh.y;
                *(float2*)(out + (size_t)rl * CCH + colc) = ol;
                *(float2*)(out + (size_t)rh * CCH + colc) = oh;
            }
        }
    }
}

extern "C" void kernel_launch(void* const* d_in, const int* in_sizes, int n_in,
                              void* d_out, int out_size)
{
    const float* U   = (const float*)d_in[0];   // [N, 64]
    const float* ref = (const float*)d_in[1];   // [N, 5]
    float* out = (float*)d_out;                 // [N, 64]
    (void)in_sizes; (void)n_in; (void)out_size;

    cudaFuncSetAttribute(lsh_mma_sj_kernel,
                         cudaFuncAttributeMaxDynamicSharedMemorySize, SMEM_TOTAL);
    lsh_mma_sj_kernel<<<N_PTS / BM, TPB, SMEM_TOTAL>>>(U, ref, out);
}

// round 8
// speedup vs baseline: 1.3038x; 1.1395x over previous
#include <cuda_runtime.h>
#include <cstdint>

// LSHGaussian, fp16 mma.sync.m16n8k16 (same 10-bit mantissa as tf32, 2x rate):
//   grid=128 CTAs x 512 threads (16 warps). Warps split the 128-j tile into
//   halves (h = wid>>3); 8 row-blocks of 16 rows (wm = wid&7). Each warp:
//   16 rows x 64 j. End: one smem reduction between j-halves.
//   U staged as f16x2 pairs (adjacent j packed), weights computed in fp32 via
//   packed f32x2 chains, emitted as f16x2 A-fragments. Double-buffered tiles.
// out = P @ U - U,  P[i,j] = exp(-0.5*||ref_i-ref_j||^2).

#define N_PTS  16384
#define CCH    64
#define BM     128
#define BK     128
#define TPB    512
#define NTILES (N_PTS / BK)
#define USTR2  72          // uint32 (f16x2) stride per jp row: banks conflict-free
#define R2STR  12          // u64 per jp row in R2

#define US_BYTES (64 * USTR2 * 4)      // 18432 per buffer (64 jp x 72 u32)
#define R2_BYTES (64 * R2STR * 8)      // 6144 per buffer
#define OFF_US0  0
#define OFF_US1  US_BYTES
#define OFF_R20  (2 * US_BYTES)
#define OFF_R21  (2 * US_BYTES + R2_BYTES)
#define SMEM_TOTAL (2 * US_BYTES + 2 * R2_BYTES)   // 49152

typedef unsigned long long u64;

__device__ __forceinline__ float ex2f(float x) {
    float r; asm("ex2.approx.ftz.f32 %0, %1;" : "=f"(r) : "f"(x)); return r;
}
#define FMA2(acc, a, b) asm("fma.rn.f32x2 %0, %1, %2, %0;" : "+l"(acc) : "l"(a), "l"(b))
#define ADD2(d, a, b)   asm("add.rn.f32x2 %0, %1, %2;" : "=l"(d) : "l"(a), "l"(b))
#define PACKB(d, f)     asm("mov.b64 %0, {%1, %1};" : "=l"(d) : "f"(f))
#define PACK2(d, lo, hi) asm("mov.b64 %0, {%1, %2};" : "=l"(d) : "f"(lo), "f"(hi))
#define UNPK(lo, hi, v) asm("mov.b64 {%0, %1}, %2;" : "=f"(lo), "=f"(hi) : "l"(v))
#define CVTH(d, hi, lo) asm("cvt.rn.f16x2.f32 %0, %1, %2;" : "=r"(d) : "f"(hi), "f"(lo))
#define MMA16(cc, a0, a1, a2, a3, b0, b1) \
    asm volatile("mma.sync.aligned.m16n8k16.row.col.f32.f16.f16.f32 " \
                 "{%0,%1,%2,%3}, {%4,%5,%6,%7}, {%8,%9}, {%0,%1,%2,%3};" \
                 : "+f"((cc)[0]), "+f"((cc)[1]), "+f"((cc)[2]), "+f"((cc)[3]) \
                 : "r"(a0), "r"(a1), "r"(a2), "r"(a3), "r"(b0), "r"(b1))

__global__ void __launch_bounds__(TPB, 1)
lsh_h16_kernel(const float* __restrict__ U, const float* __restrict__ ref,
               float* __restrict__ out)
{
    extern __shared__ __align__(16) char smem[];
    uint32_t* const UsB[2] = { (uint32_t*)(smem + OFF_US0), (uint32_t*)(smem + OFF_US1) };
    u64*      const R2B[2] = { (u64*)(smem + OFF_R20), (u64*)(smem + OFF_R21) };

    const int tid  = threadIdx.x;
    const int wid  = tid >> 5;
    const int lane = tid & 31;
    const int g    = lane >> 2;        // 0..7
    const int kin  = lane & 3;         // 0..3
    const int h    = wid >> 3;         // j-half (0/1)
    const int wm   = wid & 7;          // row-block (16 rows)
    const float L2E = 1.4426950408889634f;
    const int rbase = blockIdx.x * BM + wm * 16;

    // 2 A-rows per thread (g, g+8): packed-broadcast ri (scaled) + bias.
    u64 ri2[2][5], bi2[2];
    #pragma unroll
    for (int rr = 0; rr < 2; ++rr) {
        const float* rp = ref + (size_t)(rbase + rr * 8 + g) * 5;
        float s = 0.f;
        #pragma unroll
        for (int k = 0; k < 5; ++k) {
            float v = rp[k];
            s = fmaf(v, v, s);
            PACKB(ri2[rr][k], v * L2E);
        }
        PACKB(bi2[rr], -0.5f * L2E * s);
    }

    float c[8][4];
    #pragma unroll
    for (int nt = 0; nt < 8; ++nt)
        #pragma unroll
        for (int q = 0; q < 4; ++q) c[nt][q] = 0.f;

    // ── stage tile 0 ──
    {
        const float4* Ug = (const float4*)U;
        #pragma unroll
        for (int it = 0; it < 2; ++it) {
            int f = it * TPB + tid;        // 0..1023
            int jp = f >> 4, c4 = f & 15;
            float4 vA = Ug[(2 * jp) * 16 + c4];
            float4 vB = Ug[(2 * jp + 1) * 16 + c4];
            uint4 w;
            CVTH(w.x, vB.x, vA.x); CVTH(w.y, vB.y, vA.y);
            CVTH(w.z, vB.z, vA.z); CVTH(w.w, vB.w, vA.w);
            *(uint4*)&UsB[0][jp * USTR2 + c4 * 4] = w;
        }
        if (tid < 64) {
            const float* ra = ref + (size_t)(2 * tid) * 5;
            const float* rb = ra + 5;
            float sa = 0.f, sb = 0.f;
            u64* R = &R2B[0][tid * R2STR];
            #pragma unroll
            for (int k = 0; k < 5; ++k) {
                float a = ra[k], b = rb[k];
                sa = fmaf(a, a, sa); sb = fmaf(b, b, sb);
                PACK2(R[k], a, b);
            }
            PACK2(R[5], -0.5f * L2E * sa, -0.5f * L2E * sb);
        }
    }
    __syncthreads();

    for (int t = 0; t < NTILES; ++t) {
        const int buf = t & 1, nbuf = buf ^ 1;
        const bool pfv = (t + 1 < NTILES);

        // prefetch next tile into registers
        float4 pA[2], pB[2]; float pa[5], pb[5];
        if (pfv) {
            const float4* Ug = (const float4*)(U + (size_t)(t + 1) * BK * CCH);
            #pragma unroll
            for (int it = 0; it < 2; ++it) {
                int f = it * TPB + tid, jp = f >> 4, c4 = f & 15;
                pA[it] = Ug[(2 * jp) * 16 + c4];
                pB[it] = Ug[(2 * jp + 1) * 16 + c4];
            }
            if (tid < 64) {
                const float* ra = ref + (size_t)((t + 1) * BK + 2 * tid) * 5;
                #pragma unroll
                for (int k = 0; k < 5; ++k) { pa[k] = ra[k]; pb[k] = ra[k + 5]; }
            }
        }

        // ── compute tile t: 4 k-chunks of 16 j ──
        {
            const uint32_t* __restrict__ Ub = UsB[buf];
            const u64*      __restrict__ R2 = R2B[buf];
            const int jp0base = h * 32 + kin;
            #pragma unroll
            for (int kc = 0; kc < 4; ++kc) {
                const int jpA = jp0base + kc * 8;        // k 0..7 of chunk
                const int jpB = jpA + 4;                 // k 8..15
                const u64* Ra = &R2[jpA * R2STR];
                const u64* Rb = &R2[jpB * R2STR];
                ulonglong2 xa01 = *(const ulonglong2*)&Ra[0];
                ulonglong2 xa23 = *(const ulonglong2*)&Ra[2];
                ulonglong2 xa45 = *(const ulonglong2*)&Ra[4];
                ulonglong2 xb01 = *(const ulonglong2*)&Rb[0];
                ulonglong2 xb23 = *(const ulonglong2*)&Rb[2];
                ulonglong2 xb45 = *(const ulonglong2*)&Rb[4];

                u64 tA0, tA1, tB0, tB1;
                ADD2(tA0, xa45.y, bi2[0]); ADD2(tA1, xa45.y, bi2[1]);
                ADD2(tB0, xb45.y, bi2[0]); ADD2(tB1, xb45.y, bi2[1]);
                FMA2(tA0, ri2[0][0], xa01.x); FMA2(tA1, ri2[1][0], xa01.x);
                FMA2(tB0, ri2[0][0], xb01.x); FMA2(tB1, ri2[1][0], xb01.x);
                FMA2(tA0, ri2[0][1], xa01.y); FMA2(tA1, ri2[1][1], xa01.y);
                FMA2(tB0, ri2[0][1], xb01.y); FMA2(tB1, ri2[1][1], xb01.y);
                FMA2(tA0, ri2[0][2], xa23.x); FMA2(tA1, ri2[1][2], xa23.x);
                FMA2(tB0, ri2[0][2], xb23.x); FMA2(tB1, ri2[1][2], xb23.x);
                FMA2(tA0, ri2[0][3], xa23.y); FMA2(tA1, ri2[1][3], xa23.y);
                FMA2(tB0, ri2[0][3], xb23.y); FMA2(tB1, ri2[1][3], xb23.y);
                FMA2(tA0, ri2[0][4], xa45.x); FMA2(tA1, ri2[1][4], xa45.x);
                FMA2(tB0, ri2[0][4], xb45.x); FMA2(tB1, ri2[1][4], xb45.x);

                float e, o;
                uint32_t a0, a1, a2, a3;
                UNPK(e, o, tA0); e = ex2f(e); o = ex2f(o); CVTH(a0, o, e);
                UNPK(e, o, tA1); e = ex2f(e); o = ex2f(o); CVTH(a1, o, e);
                UNPK(e, o, tB0); e = ex2f(e); o = ex2f(o); CVTH(a2, o, e);
                UNPK(e, o, tB1); e = ex2f(e); o = ex2f(o); CVTH(a3, o, e);

                const uint32_t* u0 = &Ub[jpA * USTR2 + g];
                const uint32_t* u1 = &Ub[jpB * USTR2 + g];
                #pragma unroll
                for (int nt = 0; nt < 8; ++nt) {
                    uint32_t b0 = u0[nt * 8];
                    uint32_t b1 = u1[nt * 8];
                    MMA16(c[nt], a0, a1, a2, a3, b0, b1);
                }
            }
        }

        // ── stage tile t+1 ──
        if (pfv) {
            uint32_t* Ud = UsB[nbuf];
            #pragma unroll
            for (int it = 0; it < 2; ++it) {
                int f = it * TPB + tid, jp = f >> 4, c4 = f & 15;
                uint4 w;
                CVTH(w.x, pB[it].x, pA[it].x); CVTH(w.y, pB[it].y, pA[it].y);
                CVTH(w.z, pB[it].z, pA[it].z); CVTH(w.w, pB[it].w, pA[it].w);
                *(uint4*)&Ud[jp * USTR2 + c4 * 4] = w;
            }
            if (tid < 64) {
                float sa = 0.f, sb = 0.f;
                u64* R = &R2B[nbuf][tid * R2STR];
                #pragma unroll
                for (int k = 0; k < 5; ++k) {
                    sa = fmaf(pa[k], pa[k], sa); sb = fmaf(pb[k], pb[k], sb);
                    PACK2(R[k], pa[k], pb[k]);
                }
                PACK2(R[5], -0.5f * L2E * sa, -0.5f * L2E * sb);
            }
        }
        __syncthreads();
    }

    // ── reduce j-halves (h=1 -> h=0) via smem, then out = C - U ──
    float4* Sred = (float4*)smem;   // 8 wm x 8 nt x 32 lanes x float4 = 32 KB
    if (h == 1) {
        #pragma unroll
        for (int nt = 0; nt < 8; ++nt)
            Sred[(wm * 8 + nt) * 32 + lane] = make_float4(c[nt][0], c[nt][1],
                                                          c[nt][2], c[nt][3]);
    }
    __syncthreads();
    if (h == 0) {
        const int rl = rbase + g, rh = rl + 8;
        const int n0 = 2 * kin;
        #pragma unroll
        for (int nt = 0; nt < 8; ++nt) {
            float4 v = Sred[(wm * 8 + nt) * 32 + lane];
            const int col = nt * 8 + n0;
            float2 ul = *(const float2*)(U + (size_t)rl * CCH + col);
            float2 uh = *(const float2*)(U + (size_t)rh * CCH + col);
            float2 ol, oh;
            ol.x = (c[nt][0] + v.x) - ul.x; ol.y = (c[nt][1] + v.y) - ul.y;
            oh.x = (c[nt][2] + v.z) - uh.x; oh.y = (c[nt][3] + v.w) - uh.y;
            *(float2*)(out + (size_t)rl * CCH + col) = ol;
            *(float2*)(out + (size_t)rh * CCH + col) = oh;
        }
    }
}

extern "C" void kernel_launch(void* const* d_in, const int* in_sizes, int n_in,
                              void* d_out, int out_size)
{
    const float* U   = (const float*)d_in[0];   // [N, 64]
    const float* ref = (const float*)d_in[1];   // [N, 5]
    float* out = (float*)d_out;                 // [N, 64]
    (void)in_sizes; (void)n_in; (void)out_size;

    cudaFuncSetAttribute(lsh_h16_kernel,
                         cudaFuncAttributeMaxDynamicSharedMemorySize, SMEM_TOTAL);
    lsh_h16_kernel<<<N_PTS / BM, TPB, SMEM_TOTAL>>>(U, ref, out);
}